// round 1
// baseline (speedup 1.0000x reference)
#include <cuda_runtime.h>
#include <cuda_bf16.h>
#include <cstdint>

// Problem constants
#define NROWS 262144
#define CIN   256
#define MID   64
#define KOFF  9
#define EPS   1e-5f

// Scratch (device globals; allocation is forbidden)
__device__ float g_h2[(size_t)NROWS * MID];   // after conv1+bn2+relu
__device__ float g_h4[(size_t)NROWS * MID];   // after conv2+bn3+relu
__device__ int   g_mask_mode;                 // 0=int32 1=uint8 2=float32 3=bf16

// ---------------------------------------------------------------------------
// Mask dtype probe: classify byte pattern of first 4096 bytes.
// bool p=0.6 guarantees plenty of ones in any encoding.
// ---------------------------------------------------------------------------
__global__ void kDetect(const unsigned char* __restrict__ m) {
    if (threadIdx.x != 0 || blockIdx.x != 0) return;
    int saw3F_at1 = 0, saw3F = 0, sawNZ_nm4 = 0;
    for (int i = 0; i < 4096; i++) {
        unsigned char b = m[i];
        if (b == 0x3F) { saw3F = 1; if ((i & 3) == 1) saw3F_at1 = 1; }
        else if (b != 0 && (i & 3) != 0) sawNZ_nm4 = 1;
    }
    int mode;
    if (saw3F_at1)      mode = 3;  // bf16 (0x3F high byte at odd offsets incl. i%4==1)
    else if (saw3F)     mode = 2;  // float32 (0x3F at i%4==3)
    else if (sawNZ_nm4) mode = 1;  // uint8/bool
    else                mode = 0;  // int32
    g_mask_mode = mode;
}

__device__ __forceinline__ bool mask_on(const void* p, size_t i, int mode) {
    switch (mode) {
        case 1:  return ((const unsigned char*)p)[i] != 0;
        case 2:  return ((const float*)p)[i] != 0.0f;
        case 3:  return ((const unsigned short*)p)[i] != 0;
        default: return ((const int*)p)[i] != 0;
    }
}

// ---------------------------------------------------------------------------
// Kernel A: h2 = relu(bn2( relu(bn1(x)) @ w1 + b1 ))     [N,256]->[N,64]
// Tile: 128 rows x 64 cols, K-chunks of 32, 128 threads, 8x8 micro-tile.
// ---------------------------------------------------------------------------
__global__ void __launch_bounds__(128, 4)
kA(const float* __restrict__ x,
   const float* __restrict__ g1, const float* __restrict__ be1,
   const float* __restrict__ mu1, const float* __restrict__ va1,
   const float* __restrict__ w1, const float* __restrict__ b1,
   const float* __restrict__ g2, const float* __restrict__ be2,
   const float* __restrict__ mu2, const float* __restrict__ va2)
{
    __shared__ float Xs[32][132];     // transposed x_preact tile [k][m]
    __shared__ float Ws[32][64];      // w1 tile [k][n]
    __shared__ float s1[CIN], t1[CIN];
    __shared__ float s2[MID], u2[MID];

    const int tid = threadIdx.x;
    for (int c = tid; c < CIN; c += 128) {
        float s = g1[c] * rsqrtf(va1[c] + EPS);
        s1[c] = s; t1[c] = be1[c] - mu1[c] * s;
    }
    if (tid < MID) {
        float s = g2[tid] * rsqrtf(va2[tid] + EPS);
        s2[tid] = s;
        u2[tid] = b1[tid] * s + (be2[tid] - mu2[tid] * s);
    }

    const int m0 = blockIdx.x * 128;
    const int tx = tid & 7, ty = tid >> 3;
    float acc[8][8] = {};

    for (int kk = 0; kk < CIN; kk += 32) {
        __syncthreads();
        // x tile: 1 row per thread, bn1+relu on the fly, store transposed
        {
            const float4* xr = reinterpret_cast<const float4*>(
                x + (size_t)(m0 + tid) * CIN + kk);
            #pragma unroll
            for (int i = 0; i < 8; i++) {
                float4 v = xr[i];
                int c = kk + i * 4;
                Xs[i*4+0][tid] = fmaxf(v.x * s1[c+0] + t1[c+0], 0.0f);
                Xs[i*4+1][tid] = fmaxf(v.y * s1[c+1] + t1[c+1], 0.0f);
                Xs[i*4+2][tid] = fmaxf(v.z * s1[c+2] + t1[c+2], 0.0f);
                Xs[i*4+3][tid] = fmaxf(v.w * s1[c+3] + t1[c+3], 0.0f);
            }
        }
        // w1 tile [32][64] contiguous
        {
            const float4* wr = reinterpret_cast<const float4*>(w1 + (size_t)kk * MID);
            float4* ws = reinterpret_cast<float4*>(&Ws[0][0]);
            #pragma unroll
            for (int i = 0; i < 4; i++) ws[tid + i * 128] = wr[tid + i * 128];
        }
        __syncthreads();

        #pragma unroll 8
        for (int k = 0; k < 32; k++) {
            float4 a0 = *reinterpret_cast<const float4*>(&Xs[k][ty * 8]);
            float4 a1 = *reinterpret_cast<const float4*>(&Xs[k][ty * 8 + 4]);
            float4 b0 = *reinterpret_cast<const float4*>(&Ws[k][tx * 8]);
            float4 b1v = *reinterpret_cast<const float4*>(&Ws[k][tx * 8 + 4]);
            float a[8] = {a0.x,a0.y,a0.z,a0.w,a1.x,a1.y,a1.z,a1.w};
            float b[8] = {b0.x,b0.y,b0.z,b0.w,b1v.x,b1v.y,b1v.z,b1v.w};
            #pragma unroll
            for (int i = 0; i < 8; i++)
                #pragma unroll
                for (int j = 0; j < 8; j++)
                    acc[i][j] += a[i] * b[j];
        }
    }

    // epilogue: +b1 folded, bn2+relu, store h2
    #pragma unroll
    for (int i = 0; i < 8; i++) {
        int r = m0 + ty * 8 + i;
        float o[8];
        #pragma unroll
        for (int j = 0; j < 8; j++) {
            int cl = tx * 8 + j;
            o[j] = fmaxf(acc[i][j] * s2[cl] + u2[cl], 0.0f);
        }
        float4* dst = reinterpret_cast<float4*>(g_h2 + (size_t)r * MID + tx * 8);
        dst[0] = make_float4(o[0], o[1], o[2], o[3]);
        dst[1] = make_float4(o[4], o[5], o[6], o[7]);
    }
}

// ---------------------------------------------------------------------------
// Kernel B: gather-GEMM over 9 offsets: h3 = sum_k (masked gather of h2) @ w2[k]
// then h4 = relu(bn3(h3 + b2)). Tile 128 rows x 64 cols, 128 threads.
// ---------------------------------------------------------------------------
__global__ void __launch_bounds__(128, 4)
kB(const float* __restrict__ w2, const float* __restrict__ b2,
   const float* __restrict__ g3, const float* __restrict__ be3,
   const float* __restrict__ mu3, const float* __restrict__ va3,
   const int* __restrict__ nbr, const void* __restrict__ maskp)
{
    extern __shared__ float sm[];
    float* Gs  = sm;                 // [64][132] transposed gathered tile
    float* W2s = sm + 64 * 132;      // [64][64]
    float* s3  = W2s + 64 * 64;      // [64]
    float* u3  = s3 + 64;            // [64]

    const int tid = threadIdx.x;
    if (tid < MID) {
        float s = g3[tid] * rsqrtf(va3[tid] + EPS);
        s3[tid] = s;
        u3[tid] = b2[tid] * s + (be3[tid] - mu3[tid] * s);
    }

    const int m0 = blockIdx.x * 128;
    const int row = m0 + tid;
    const int mode = g_mask_mode;
    const int tx = tid & 7, ty = tid >> 3;
    float acc[8][8] = {};

    for (int k = 0; k < KOFF; k++) {
        __syncthreads();
        // w2[k] tile: 64x64 contiguous
        {
            const float4* wr = reinterpret_cast<const float4*>(w2 + (size_t)k * 4096);
            float4* ws = reinterpret_cast<float4*>(W2s);
            #pragma unroll
            for (int i = 0; i < 8; i++) ws[tid + i * 128] = wr[tid + i * 128];
        }
        // gather one h2 row per thread (L2-resident table), store transposed
        {
            size_t e = (size_t)row * KOFF + k;
            int idx = nbr[e];
            if (mask_on(maskp, e, mode)) {
                const float4* hr = reinterpret_cast<const float4*>(g_h2 + (size_t)idx * MID);
                #pragma unroll
                for (int i = 0; i < 16; i++) {
                    float4 v = hr[i];
                    Gs[(i*4+0)*132 + tid] = v.x;
                    Gs[(i*4+1)*132 + tid] = v.y;
                    Gs[(i*4+2)*132 + tid] = v.z;
                    Gs[(i*4+3)*132 + tid] = v.w;
                }
            } else {
                #pragma unroll
                for (int c = 0; c < 64; c++) Gs[c * 132 + tid] = 0.0f;
            }
        }
        __syncthreads();

        #pragma unroll 8
        for (int c = 0; c < 64; c++) {
            float4 a0 = *reinterpret_cast<const float4*>(&Gs[c * 132 + ty * 8]);
            float4 a1 = *reinterpret_cast<const float4*>(&Gs[c * 132 + ty * 8 + 4]);
            float4 b0 = *reinterpret_cast<const float4*>(&W2s[c * 64 + tx * 8]);
            float4 b1v = *reinterpret_cast<const float4*>(&W2s[c * 64 + tx * 8 + 4]);
            float a[8] = {a0.x,a0.y,a0.z,a0.w,a1.x,a1.y,a1.z,a1.w};
            float b[8] = {b0.x,b0.y,b0.z,b0.w,b1v.x,b1v.y,b1v.z,b1v.w};
            #pragma unroll
            for (int i = 0; i < 8; i++)
                #pragma unroll
                for (int j = 0; j < 8; j++)
                    acc[i][j] += a[i] * b[j];
        }
    }

    // epilogue: +b2 folded, bn3+relu, store h4
    #pragma unroll
    for (int i = 0; i < 8; i++) {
        int r = m0 + ty * 8 + i;
        float o[8];
        #pragma unroll
        for (int j = 0; j < 8; j++) {
            int cl = tx * 8 + j;
            o[j] = fmaxf(acc[i][j] * s3[cl] + u3[cl], 0.0f);
        }
        float4* dst = reinterpret_cast<float4*>(g_h4 + (size_t)r * MID + tx * 8);
        dst[0] = make_float4(o[0], o[1], o[2], o[3]);
        dst[1] = make_float4(o[4], o[5], o[6], o[7]);
    }
}

// ---------------------------------------------------------------------------
// Kernel C: out = h4 @ w3 + b3 + relu(bn1(x))   [N,64]->[N,256]
// Grid (rowtiles, 4 coltiles of 64). Tile 128x64, 128 threads.
// ---------------------------------------------------------------------------
__global__ void __launch_bounds__(128, 4)
kC(const float* __restrict__ x,
   const float* __restrict__ g1, const float* __restrict__ be1,
   const float* __restrict__ mu1, const float* __restrict__ va1,
   const float* __restrict__ w3, const float* __restrict__ b3,
   float* __restrict__ out)
{
    extern __shared__ float sm[];
    float* Hs  = sm;                  // [64][132] transposed h4 tile
    float* W3s = sm + 64 * 132;       // [64][64]
    float* s1c = W3s + 64 * 64;
    float* t1c = s1c + 64;
    float* b3c = t1c + 64;

    const int tid = threadIdx.x;
    const int m0 = blockIdx.x * 128;
    const int c0 = blockIdx.y * 64;

    if (tid < 64) {
        int c = c0 + tid;
        float s = g1[c] * rsqrtf(va1[c] + EPS);
        s1c[tid] = s; t1c[tid] = be1[c] - mu1[c] * s; b3c[tid] = b3[c];
    }
    // h4 tile transposed
    {
        const float4* hr = reinterpret_cast<const float4*>(g_h4 + (size_t)(m0 + tid) * MID);
        #pragma unroll
        for (int i = 0; i < 16; i++) {
            float4 v = hr[i];
            Hs[(i*4+0)*132 + tid] = v.x;
            Hs[(i*4+1)*132 + tid] = v.y;
            Hs[(i*4+2)*132 + tid] = v.z;
            Hs[(i*4+3)*132 + tid] = v.w;
        }
    }
    // w3 slice [64 rows][cols c0..c0+63]
    {
        #pragma unroll
        for (int i = 0; i < 8; i++) {
            int lin = tid + i * 128;             // float4 index, 0..1023
            int c = lin >> 4, n4 = lin & 15;
            float4 v = *reinterpret_cast<const float4*>(
                w3 + (size_t)c * CIN + c0 + n4 * 4);
            *reinterpret_cast<float4*>(&W3s[c * 64 + n4 * 4]) = v;
        }
    }
    __syncthreads();

    const int tx = tid & 7, ty = tid >> 3;
    float acc[8][8] = {};
    #pragma unroll 8
    for (int c = 0; c < 64; c++) {
        float4 a0 = *reinterpret_cast<const float4*>(&Hs[c * 132 + ty * 8]);
        float4 a1 = *reinterpret_cast<const float4*>(&Hs[c * 132 + ty * 8 + 4]);
        float4 b0 = *reinterpret_cast<const float4*>(&W3s[c * 64 + tx * 8]);
        float4 b1v = *reinterpret_cast<const float4*>(&W3s[c * 64 + tx * 8 + 4]);
        float a[8] = {a0.x,a0.y,a0.z,a0.w,a1.x,a1.y,a1.z,a1.w};
        float b[8] = {b0.x,b0.y,b0.z,b0.w,b1v.x,b1v.y,b1v.z,b1v.w};
        #pragma unroll
        for (int i = 0; i < 8; i++)
            #pragma unroll
            for (int j = 0; j < 8; j++)
                acc[i][j] += a[i] * b[j];
    }

    // epilogue: + b3 + shortcut (recompute bn1+relu from x), store out
    #pragma unroll
    for (int i = 0; i < 8; i++) {
        int r = m0 + ty * 8 + i;
        const float4* xr = reinterpret_cast<const float4*>(
            x + (size_t)r * CIN + c0 + tx * 8);
        float4 x0 = xr[0], x1 = xr[1];
        float xv[8] = {x0.x,x0.y,x0.z,x0.w,x1.x,x1.y,x1.z,x1.w};
        float o[8];
        #pragma unroll
        for (int j = 0; j < 8; j++) {
            int cl = tx * 8 + j;
            o[j] = acc[i][j] + b3c[cl] + fmaxf(xv[j] * s1c[cl] + t1c[cl], 0.0f);
        }
        float4* dst = reinterpret_cast<float4*>(out + (size_t)r * CIN + c0 + tx * 8);
        dst[0] = make_float4(o[0], o[1], o[2], o[3]);
        dst[1] = make_float4(o[4], o[5], o[6], o[7]);
    }
}

// ---------------------------------------------------------------------------
extern "C" void kernel_launch(void* const* d_in, const int* in_sizes, int n_in,
                              void* d_out, int out_size)
{
    const float* x        = (const float*)d_in[0];
    const float* bn1_g    = (const float*)d_in[1];
    const float* bn1_b    = (const float*)d_in[2];
    const float* bn1_m    = (const float*)d_in[3];
    const float* bn1_v    = (const float*)d_in[4];
    const float* w1       = (const float*)d_in[5];
    const float* b1       = (const float*)d_in[6];
    const float* bn2_g    = (const float*)d_in[7];
    const float* bn2_b    = (const float*)d_in[8];
    const float* bn2_m    = (const float*)d_in[9];
    const float* bn2_v    = (const float*)d_in[10];
    const float* w2       = (const float*)d_in[11];
    const float* b2       = (const float*)d_in[12];
    const float* bn3_g    = (const float*)d_in[13];
    const float* bn3_b    = (const float*)d_in[14];
    const float* bn3_m    = (const float*)d_in[15];
    const float* bn3_v    = (const float*)d_in[16];
    const float* w3       = (const float*)d_in[17];
    const float* b3       = (const float*)d_in[18];
    const int*   nbr_idx  = (const int*)d_in[19];
    const void*  nbr_mask = (const void*)d_in[20];
    float* out = (float*)d_out;

    const size_t SMB = (size_t)(64 * 132 + 64 * 64 + 128) * sizeof(float);
    const size_t SMC = (size_t)(64 * 132 + 64 * 64 + 192) * sizeof(float);
    cudaFuncSetAttribute(kB, cudaFuncAttributeMaxDynamicSharedMemorySize, (int)SMB);
    cudaFuncSetAttribute(kC, cudaFuncAttributeMaxDynamicSharedMemorySize, (int)SMC);

    kDetect<<<1, 1>>>((const unsigned char*)nbr_mask);
    kA<<<NROWS / 128, 128>>>(x, bn1_g, bn1_b, bn1_m, bn1_v, w1, b1,
                             bn2_g, bn2_b, bn2_m, bn2_v);
    kB<<<NROWS / 128, 128, SMB>>>(w2, b2, bn3_g, bn3_b, bn3_m, bn3_v,
                                  nbr_idx, nbr_mask);
    kC<<<dim3(NROWS / 128, 4), 128, SMC>>>(x, bn1_g, bn1_b, bn1_m, bn1_v,
                                           w3, b3, out);
    (void)in_sizes; (void)n_in; (void)out_size;
}